// round 2
// baseline (speedup 1.0000x reference)
#include <cuda_runtime.h>
#include <cstdint>

#define N_ATOM 50000
#define M_NBR  12
#define NM_TOT 600000
#define F_DIM  128
#define FAN_IN 320
#define EPS    1e-5f
#define CH     25

// ---------------- scratch (static __device__, no allocation) ----------------
__device__ __align__(16) float g_SA[(size_t)N_ATOM * 512];      // [n][0:256)=S, [256:512)=A
__device__ __align__(16) float g_gated[(size_t)NM_TOT * 256];   // pre-BN gated
__device__ __align__(16) float g_nbr[(size_t)N_ATOM * F_DIM];   // nbr_sumed
__device__ float g_stats1[512];                   // sum[256], sumsq[256]
__device__ float g_stats2[256];                   // sum[128], sumsq[128]
__device__ float g_bn1[512];                      // scale[256], shift[256]
__device__ float g_bn2[256];                      // scale[128], shift[128]
__device__ int   g_idx32[NM_TOT];                 // normalized int32 indices
__device__ int   g_is64;                          // 1 if input idx is int64

__device__ __forceinline__ float softplusf(float x) {
    return fmaxf(x, 0.f) + log1pf(__expf(-fabsf(x)));
}
__device__ __forceinline__ float sigmoidf(float x) {
    return 1.f / (1.f + __expf(-x));
}

// ---------------- k_detect: is idx int64 or int32? --------------------------
// Sample first 256 odd 32-bit words. int64 data: high words, all zero
// (values < 2^31). int32 data: random idx values, P(all zero) ~ (1/50000)^256.
__global__ void k_detect(const int* __restrict__ raw) {
    __shared__ int any;
    if (threadIdx.x == 0) any = 0;
    __syncthreads();
    if (raw[threadIdx.x * 2 + 1] != 0) atomicOr(&any, 1);
    __syncthreads();
    if (threadIdx.x == 0) g_is64 = any ? 0 : 1;
}

// ---------------- k_convert: normalize idx to int32 + reset stats -----------
__global__ void k_convert(const int* __restrict__ raw) {
    int i = blockIdx.x * blockDim.x + threadIdx.x;
    if (i < NM_TOT) {
        // int64 little-endian: value i lives in word 2*i (high word 2*i+1 is 0)
        g_idx32[i] = g_is64 ? raw[2 * i] : raw[i];
    }
    if (i < 512) g_stats1[i] = 0.f;
    if (i < 256) g_stats2[i] = 0.f;
}

// ---------------- k1: [S|A] = atom @ [W_self|W_nbr]^T  (50000x512, K=128) ---
__global__ __launch_bounds__(256) void k_gemm_sa(const float* __restrict__ atom,
                                                 const float* __restrict__ W) {
    __shared__ float Xs[64][64];    // [row][k]
    __shared__ float Ws[64][128];   // [k][f]
    const int tid = threadIdx.x;
    const int tx = tid & 31, ty = tid >> 5;
    const int fbase = blockIdx.x * 128;               // 0..511 step 128
    const int row0  = blockIdx.y * 64;
    const int wfbase = (blockIdx.x < 2) ? fbase : fbase - 256;
    const int wkoff  = (blockIdx.x < 2) ? 0 : 128;

    float c[8][4];
#pragma unroll
    for (int i = 0; i < 8; i++)
#pragma unroll
        for (int j = 0; j < 4; j++) c[i][j] = 0.f;

    for (int kc = 0; kc < 128; kc += 64) {
        for (int t = tid; t < 64 * 16; t += 256) {
            int r = t >> 4, kq = t & 15;
            int gr = row0 + r;
            float4 v = make_float4(0.f, 0.f, 0.f, 0.f);
            if (gr < N_ATOM)
                v = *(const float4*)(atom + (size_t)gr * 128 + kc + kq * 4);
            *(float4*)&Xs[r][kq * 4] = v;
        }
        for (int t = tid; t < 128 * 16; t += 256) {
            int fl = t & 127, kq = t >> 7;
            float4 v = *(const float4*)(W + (size_t)(wfbase + fl) * FAN_IN + wkoff + kc + kq * 4);
            Ws[kq * 4 + 0][fl] = v.x; Ws[kq * 4 + 1][fl] = v.y;
            Ws[kq * 4 + 2][fl] = v.z; Ws[kq * 4 + 3][fl] = v.w;
        }
        __syncthreads();
#pragma unroll 8
        for (int k = 0; k < 64; k++) {
            float4 b = *(float4*)&Ws[k][tx * 4];
#pragma unroll
            for (int i = 0; i < 8; i++) {
                float a = Xs[ty * 8 + i][k];
                c[i][0] += a * b.x; c[i][1] += a * b.y;
                c[i][2] += a * b.z; c[i][3] += a * b.w;
            }
        }
        __syncthreads();
    }
#pragma unroll
    for (int i = 0; i < 8; i++) {
        int gr = row0 + ty * 8 + i;
        if (gr < N_ATOM)
            *(float4*)(g_SA + (size_t)gr * 512 + fbase + tx * 4) =
                make_float4(c[i][0], c[i][1], c[i][2], c[i][3]);
    }
}

// ---------------- k2: E = nbr @ W_edge^T, fused gated + BN1 stats -----------
__global__ __launch_bounds__(256) void k_gemm_gate(const float* __restrict__ nbr,
                                                   const float* __restrict__ W,
                                                   const float* __restrict__ bias) {
    __shared__ float Xs[64][64];
    __shared__ float Ws[64][128];
    const int tid = threadIdx.x;
    const int tx = tid & 31, ty = tid >> 5;
    const int fbase = blockIdx.x * 128;   // 0 or 128
    const int row0  = blockIdx.y * 64;    // nm base (exact multiple)

    for (int t = tid; t < 64 * 16; t += 256) {
        int r = t >> 4, kq = t & 15;
        *(float4*)&Xs[r][kq * 4] =
            *(const float4*)(nbr + (size_t)(row0 + r) * 64 + kq * 4);
    }
    for (int t = tid; t < 128 * 16; t += 256) {
        int fl = t & 127, kq = t >> 7;
        float4 v = *(const float4*)(W + (size_t)(fbase + fl) * FAN_IN + 256 + kq * 4);
        Ws[kq * 4 + 0][fl] = v.x; Ws[kq * 4 + 1][fl] = v.y;
        Ws[kq * 4 + 2][fl] = v.z; Ws[kq * 4 + 3][fl] = v.w;
    }
    __syncthreads();

    float c[8][4];
#pragma unroll
    for (int i = 0; i < 8; i++)
#pragma unroll
        for (int j = 0; j < 4; j++) c[i][j] = 0.f;

#pragma unroll 8
    for (int k = 0; k < 64; k++) {
        float4 b = *(float4*)&Ws[k][tx * 4];
#pragma unroll
        for (int i = 0; i < 8; i++) {
            float a = Xs[ty * 8 + i][k];
            c[i][0] += a * b.x; c[i][1] += a * b.y;
            c[i][2] += a * b.z; c[i][3] += a * b.w;
        }
    }
    __syncthreads();

    // reuse Xs as stats buffers (256 floats: sum[128], sumsq[128])
    float* s_sum = &Xs[0][0];
    float* s_sq  = s_sum + 128;
    ((float*)&Xs[0][0])[tid] = 0.f;
    __syncthreads();

    float4 b4 = *(const float4*)(bias + fbase + tx * 4);
#pragma unroll
    for (int i = 0; i < 8; i++) {
        int nm = row0 + ty * 8 + i;
        int n = nm / 12;
        int j = g_idx32[nm];
        float msk = (j != 0) ? 1.f : 0.f;
        float4 s4 = *(const float4*)(g_SA + (size_t)n * 512 + fbase + tx * 4);
        float4 a4 = *(const float4*)(g_SA + (size_t)j * 512 + 256 + fbase + tx * 4);
        float g0 = s4.x + b4.x + msk * (a4.x + c[i][0]);
        float g1 = s4.y + b4.y + msk * (a4.y + c[i][1]);
        float g2 = s4.z + b4.z + msk * (a4.z + c[i][2]);
        float g3 = s4.w + b4.w + msk * (a4.w + c[i][3]);
        *(float4*)(g_gated + (size_t)nm * 256 + fbase + tx * 4) =
            make_float4(g0, g1, g2, g3);
        atomicAdd(&s_sum[tx * 4 + 0], g0); atomicAdd(&s_sq[tx * 4 + 0], g0 * g0);
        atomicAdd(&s_sum[tx * 4 + 1], g1); atomicAdd(&s_sq[tx * 4 + 1], g1 * g1);
        atomicAdd(&s_sum[tx * 4 + 2], g2); atomicAdd(&s_sq[tx * 4 + 2], g2 * g2);
        atomicAdd(&s_sum[tx * 4 + 3], g3); atomicAdd(&s_sq[tx * 4 + 3], g3 * g3);
    }
    __syncthreads();
    if (tid < 128) {
        atomicAdd(&g_stats1[fbase + tid],       s_sum[tid]);
        atomicAdd(&g_stats1[256 + fbase + tid], s_sq[tid]);
    }
}

// ---------------- k3: finalize BN1 affine ------------------------------------
__global__ void k_fin1(const float* __restrict__ gamma1, const float* __restrict__ beta1) {
    int f = threadIdx.x;  // 256
    float inv = 1.f / (float)NM_TOT;
    float mean = g_stats1[f] * inv;
    float var  = g_stats1[256 + f] * inv - mean * mean;
    float sc = gamma1[f] * rsqrtf(var + EPS);
    g_bn1[f] = sc;
    g_bn1[256 + f] = beta1[f] - mean * sc;
}

// ---------------- k4: gate + sum over M + BN2 stats --------------------------
__global__ __launch_bounds__(128) void k_reduce() {
    const int f = threadIdx.x;             // feature 0..127
    const int n0 = blockIdx.x * CH;
    const float sc_f = g_bn1[f],        sh_f = g_bn1[256 + f];
    const float sc_c = g_bn1[128 + f],  sh_c = g_bn1[256 + 128 + f];
    float bs = 0.f, bq = 0.f;
    for (int n = n0; n < n0 + CH; n++) {
        float acc = 0.f;
#pragma unroll
        for (int m = 0; m < 12; m++) {
            int nm = n * 12 + m;
            int j = g_idx32[nm];
            if (j != 0) {
                float gf = g_gated[(size_t)nm * 256 + f]       * sc_f + sh_f;
                float gc = g_gated[(size_t)nm * 256 + 128 + f] * sc_c + sh_c;
                acc += sigmoidf(gf) * softplusf(gc);
            }
        }
        g_nbr[(size_t)n * 128 + f] = acc;
        bs += acc; bq += acc * acc;
    }
    atomicAdd(&g_stats2[f],       bs);
    atomicAdd(&g_stats2[128 + f], bq);
}

// ---------------- k5: finalize BN2 affine ------------------------------------
__global__ void k_fin2(const float* __restrict__ gamma2, const float* __restrict__ beta2) {
    int f = threadIdx.x;  // 128
    float inv = 1.f / (float)N_ATOM;
    float mean = g_stats2[f] * inv;
    float var  = g_stats2[128 + f] * inv - mean * mean;
    float sc = gamma2[f] * rsqrtf(var + EPS);
    g_bn2[f] = sc;
    g_bn2[128 + f] = beta2[f] - mean * sc;
}

// ---------------- k6: out = softplus(atom + BN2(nbr_sumed)) ------------------
__global__ void k_out(const float* __restrict__ atom, float* __restrict__ out) {
    int i = blockIdx.x * blockDim.x + threadIdx.x;
    if (i < N_ATOM * 128) {
        int f = i & 127;
        float v = atom[i] + g_nbr[i] * g_bn2[f] + g_bn2[128 + f];
        out[i] = softplusf(v);
    }
}

// ---------------- launch ------------------------------------------------------
extern "C" void kernel_launch(void* const* d_in, const int* in_sizes, int n_in,
                              void* d_out, int out_size) {
    const float* atom   = (const float*)d_in[0];
    const float* nbr    = (const float*)d_in[1];
    const int*   idxraw = (const int*)d_in[2];
    const float* W      = (const float*)d_in[3];
    const float* b      = (const float*)d_in[4];
    const float* gamma1 = (const float*)d_in[5];
    const float* beta1  = (const float*)d_in[6];
    const float* gamma2 = (const float*)d_in[7];
    const float* beta2  = (const float*)d_in[8];
    float* out = (float*)d_out;

    k_detect<<<1, 256>>>(idxraw);
    k_convert<<<(NM_TOT + 255) / 256, 256>>>(idxraw);
    k_gemm_sa<<<dim3(4, (N_ATOM + 63) / 64), 256>>>(atom, W);
    k_gemm_gate<<<dim3(2, NM_TOT / 64), 256>>>(nbr, W, b);
    k_fin1<<<1, 256>>>(gamma1, beta1);
    k_reduce<<<N_ATOM / CH, 128>>>();
    k_fin2<<<1, 128>>>(gamma2, beta2);
    k_out<<<(N_ATOM * 128 + 255) / 256, 256>>>(atom, out);
}

// round 3
// speedup vs baseline: 1.2435x; 1.2435x over previous
#include <cuda_runtime.h>
#include <cstdint>

#define N_ATOM 50000
#define M_NBR  12
#define NM_TOT 600000
#define F_DIM  128
#define FAN_IN 320
#define EPS    1e-5f
#define CH     25

typedef unsigned long long ull;

#define PACK_F32X2(out, lo, hi) \
    asm("mov.b64 %0, {%1, %2};" : "=l"(out) : "f"(lo), "f"(hi))
#define UNPACK_F32X2(lo, hi, in) \
    asm("mov.b64 {%0, %1}, %2;" : "=f"(lo), "=f"(hi) : "l"(in))
#define FMA_F32X2(acc, a, b) \
    asm("fma.rn.f32x2 %0, %1, %2, %0;" : "+l"(acc) : "l"(a), "l"(b))

// ---------------- scratch (static __device__, no allocation) ----------------
__device__ __align__(16) float g_SA[(size_t)N_ATOM * 512];      // [n][0:256)=S, [256:512)=A
__device__ __align__(16) float g_gated[(size_t)NM_TOT * 256];   // pre-BN gated
__device__ __align__(16) float g_nbr[(size_t)N_ATOM * F_DIM];   // nbr_sumed
__device__ float g_stats1[512];                   // sum[256], sumsq[256]
__device__ float g_stats2[256];                   // sum[128], sumsq[128]
__device__ float g_bn1[512];                      // scale[256], shift[256]
__device__ float g_bn2[256];                      // scale[128], shift[128]
__device__ int   g_idx32[NM_TOT];                 // normalized int32 indices
__device__ int   g_is64;                          // 1 if input idx is int64

__device__ __forceinline__ float softplusf(float x) {
    return fmaxf(x, 0.f) + log1pf(__expf(-fabsf(x)));
}
__device__ __forceinline__ float sigmoidf(float x) {
    return 1.f / (1.f + __expf(-x));
}

// ---------------- k_detect: is idx int64 or int32? --------------------------
__global__ void k_detect(const int* __restrict__ raw) {
    __shared__ int any;
    if (threadIdx.x == 0) any = 0;
    __syncthreads();
    if (raw[threadIdx.x * 2 + 1] != 0) atomicOr(&any, 1);
    __syncthreads();
    if (threadIdx.x == 0) g_is64 = any ? 0 : 1;
}

// ---------------- k_convert: normalize idx to int32 + reset stats -----------
__global__ void k_convert(const int* __restrict__ raw) {
    int i = blockIdx.x * blockDim.x + threadIdx.x;
    if (i < NM_TOT) {
        g_idx32[i] = g_is64 ? raw[2 * i] : raw[i];
    }
    if (i < 512) g_stats1[i] = 0.f;
    if (i < 256) g_stats2[i] = 0.f;
}

// ---------------- k1: [S|A] = atom @ [W_self|W_nbr]^T  (50000x512, K=128) ---
__global__ __launch_bounds__(256) void k_gemm_sa(const float* __restrict__ atom,
                                                 const float* __restrict__ W) {
    __shared__ float Xs[64][64];    // [row][k]
    __shared__ float Ws[64][128];   // [k][f]
    const int tid = threadIdx.x;
    const int tx = tid & 31, ty = tid >> 5;
    const int fbase = blockIdx.x * 128;
    const int row0  = blockIdx.y * 64;
    const int wfbase = (blockIdx.x < 2) ? fbase : fbase - 256;
    const int wkoff  = (blockIdx.x < 2) ? 0 : 128;

    float c[8][4];
#pragma unroll
    for (int i = 0; i < 8; i++)
#pragma unroll
        for (int j = 0; j < 4; j++) c[i][j] = 0.f;

    for (int kc = 0; kc < 128; kc += 64) {
        for (int t = tid; t < 64 * 16; t += 256) {
            int r = t >> 4, kq = t & 15;
            int gr = row0 + r;
            float4 v = make_float4(0.f, 0.f, 0.f, 0.f);
            if (gr < N_ATOM)
                v = *(const float4*)(atom + (size_t)gr * 128 + kc + kq * 4);
            *(float4*)&Xs[r][kq * 4] = v;
        }
        for (int t = tid; t < 128 * 16; t += 256) {
            int fl = t & 127, kq = t >> 7;
            float4 v = *(const float4*)(W + (size_t)(wfbase + fl) * FAN_IN + wkoff + kc + kq * 4);
            Ws[kq * 4 + 0][fl] = v.x; Ws[kq * 4 + 1][fl] = v.y;
            Ws[kq * 4 + 2][fl] = v.z; Ws[kq * 4 + 3][fl] = v.w;
        }
        __syncthreads();
#pragma unroll 8
        for (int k = 0; k < 64; k++) {
            float4 b = *(float4*)&Ws[k][tx * 4];
#pragma unroll
            for (int i = 0; i < 8; i++) {
                float a = Xs[ty * 8 + i][k];
                c[i][0] += a * b.x; c[i][1] += a * b.y;
                c[i][2] += a * b.z; c[i][3] += a * b.w;
            }
        }
        __syncthreads();
    }
#pragma unroll
    for (int i = 0; i < 8; i++) {
        int gr = row0 + ty * 8 + i;
        if (gr < N_ATOM)
            *(float4*)(g_SA + (size_t)gr * 512 + fbase + tx * 4) =
                make_float4(c[i][0], c[i][1], c[i][2], c[i][3]);
    }
}

// ---------------- k2: E = nbr @ W_edge^T, fused gated + BN1 stats -----------
// BM=128 nm-rows, BN=128 features (2 x-blocks), K=64 in 2 chunks of 32.
// 256 threads: tx=tid&15 (cols tx*4, 64+tx*4), ty=tid>>4 (rows ty*4, 64+ty*4).
// 8x8 per-thread tile with fma.rn.f32x2 packed math.
__global__ __launch_bounds__(256) void k_gemm_gate(const float* __restrict__ nbr,
                                                   const float* __restrict__ W,
                                                   const float* __restrict__ bias) {
    __shared__ float Xs[32][128];   // [k][row]
    __shared__ float Ws[32][128];   // [k][f]
    __shared__ float s_stat[256];   // sum[128], sumsq[128]
    const int tid = threadIdx.x;
    const int tx = tid & 15, ty = tid >> 4;
    const int fbase = blockIdx.x * 128;   // 0 or 128
    const int row0  = blockIdx.y * 128;   // nm base (last block partial)

    ull acc[8][4];                         // [row][colpair] packed f32x2
#pragma unroll
    for (int i = 0; i < 8; i++)
#pragma unroll
        for (int j = 0; j < 4; j++) acc[i][j] = 0ULL;

    for (int kc = 0; kc < 64; kc += 32) {
        // load X transposed: 128 rows x 32 k
        for (int t = tid; t < 1024; t += 256) {
            int r = t & 127, kq = t >> 7;           // kq 0..7
            int gr = row0 + r; if (gr >= NM_TOT) gr = NM_TOT - 1;
            float4 v = *(const float4*)(nbr + (size_t)gr * 64 + kc + kq * 4);
            Xs[kq * 4 + 0][r] = v.x; Xs[kq * 4 + 1][r] = v.y;
            Xs[kq * 4 + 2][r] = v.z; Xs[kq * 4 + 3][r] = v.w;
        }
        // load W: 32 k x 128 f
        for (int t = tid; t < 1024; t += 256) {
            int fl = t & 127, kq = t >> 7;
            float4 v = *(const float4*)(W + (size_t)(fbase + fl) * FAN_IN + 256 + kc + kq * 4);
            Ws[kq * 4 + 0][fl] = v.x; Ws[kq * 4 + 1][fl] = v.y;
            Ws[kq * 4 + 2][fl] = v.z; Ws[kq * 4 + 3][fl] = v.w;
        }
        __syncthreads();
#pragma unroll 8
        for (int k = 0; k < 32; k++) {
            float4 A0 = *(float4*)&Xs[k][ty * 4];
            float4 A1 = *(float4*)&Xs[k][64 + ty * 4];
            float4 B0 = *(float4*)&Ws[k][tx * 4];
            float4 B1 = *(float4*)&Ws[k][64 + tx * 4];
            ull bb[4];
            PACK_F32X2(bb[0], B0.x, B0.y); PACK_F32X2(bb[1], B0.z, B0.w);
            PACK_F32X2(bb[2], B1.x, B1.y); PACK_F32X2(bb[3], B1.z, B1.w);
            float av[8] = {A0.x, A0.y, A0.z, A0.w, A1.x, A1.y, A1.z, A1.w};
#pragma unroll
            for (int i = 0; i < 8; i++) {
                ull aa; PACK_F32X2(aa, av[i], av[i]);
                FMA_F32X2(acc[i][0], aa, bb[0]);
                FMA_F32X2(acc[i][1], aa, bb[1]);
                FMA_F32X2(acc[i][2], aa, bb[2]);
                FMA_F32X2(acc[i][3], aa, bb[3]);
            }
        }
        __syncthreads();
    }

    // epilogue: gated = S + b + msk*(A[idx] + E); store + BN1 stats
    if (tid < 256) s_stat[tid] = 0.f;
    __syncthreads();

    float4 bia0 = *(const float4*)(bias + fbase + tx * 4);
    float4 bia1 = *(const float4*)(bias + fbase + 64 + tx * 4);
    float sums[8], sqs[8];
#pragma unroll
    for (int q = 0; q < 8; q++) { sums[q] = 0.f; sqs[q] = 0.f; }

#pragma unroll
    for (int i = 0; i < 8; i++) {
        int r = (i < 4) ? (ty * 4 + i) : (64 + ty * 4 + (i - 4));
        int nm = row0 + r;
        if (nm >= NM_TOT) continue;
        int n = nm / 12;
        int j = g_idx32[nm];
        float msk = (j != 0) ? 1.f : 0.f;
        float e[8];
        UNPACK_F32X2(e[0], e[1], acc[i][0]);
        UNPACK_F32X2(e[2], e[3], acc[i][1]);
        UNPACK_F32X2(e[4], e[5], acc[i][2]);
        UNPACK_F32X2(e[6], e[7], acc[i][3]);
#pragma unroll
        for (int cg = 0; cg < 2; cg++) {
            int col = fbase + cg * 64 + tx * 4;
            float4 s4 = *(const float4*)(g_SA + (size_t)n * 512 + col);
            float4 a4 = *(const float4*)(g_SA + (size_t)j * 512 + 256 + col);
            float4 bb4 = cg ? bia1 : bia0;
            float g0 = s4.x + bb4.x + msk * (a4.x + e[cg * 4 + 0]);
            float g1 = s4.y + bb4.y + msk * (a4.y + e[cg * 4 + 1]);
            float g2 = s4.z + bb4.z + msk * (a4.z + e[cg * 4 + 2]);
            float g3 = s4.w + bb4.w + msk * (a4.w + e[cg * 4 + 3]);
            *(float4*)(g_gated + (size_t)nm * 256 + col) = make_float4(g0, g1, g2, g3);
            sums[cg * 4 + 0] += g0; sqs[cg * 4 + 0] += g0 * g0;
            sums[cg * 4 + 1] += g1; sqs[cg * 4 + 1] += g1 * g1;
            sums[cg * 4 + 2] += g2; sqs[cg * 4 + 2] += g2 * g2;
            sums[cg * 4 + 3] += g3; sqs[cg * 4 + 3] += g3 * g3;
        }
    }
#pragma unroll
    for (int q = 0; q < 8; q++) {
        int lc = (q >> 2) * 64 + tx * 4 + (q & 3);   // local col in [0,128)
        atomicAdd(&s_stat[lc], sums[q]);
        atomicAdd(&s_stat[128 + lc], sqs[q]);
    }
    __syncthreads();
    if (tid < 128) {
        atomicAdd(&g_stats1[fbase + tid],       s_stat[tid]);
        atomicAdd(&g_stats1[256 + fbase + tid], s_stat[128 + tid]);
    }
}

// ---------------- k3: finalize BN1 affine ------------------------------------
__global__ void k_fin1(const float* __restrict__ gamma1, const float* __restrict__ beta1) {
    int f = threadIdx.x;  // 256
    float inv = 1.f / (float)NM_TOT;
    float mean = g_stats1[f] * inv;
    float var  = g_stats1[256 + f] * inv - mean * mean;
    float sc = gamma1[f] * rsqrtf(var + EPS);
    g_bn1[f] = sc;
    g_bn1[256 + f] = beta1[f] - mean * sc;
}

// ---------------- k4: gate + sum over M + BN2 stats --------------------------
__global__ __launch_bounds__(128) void k_reduce() {
    const int f = threadIdx.x;
    const int n0 = blockIdx.x * CH;
    const float sc_f = g_bn1[f],        sh_f = g_bn1[256 + f];
    const float sc_c = g_bn1[128 + f],  sh_c = g_bn1[256 + 128 + f];
    float bs = 0.f, bq = 0.f;
    for (int n = n0; n < n0 + CH; n++) {
        float acc = 0.f;
#pragma unroll
        for (int m = 0; m < 12; m++) {
            int nm = n * 12 + m;
            int j = g_idx32[nm];
            if (j != 0) {
                float gf = g_gated[(size_t)nm * 256 + f]       * sc_f + sh_f;
                float gc = g_gated[(size_t)nm * 256 + 128 + f] * sc_c + sh_c;
                acc += sigmoidf(gf) * softplusf(gc);
            }
        }
        g_nbr[(size_t)n * 128 + f] = acc;
        bs += acc; bq += acc * acc;
    }
    atomicAdd(&g_stats2[f],       bs);
    atomicAdd(&g_stats2[128 + f], bq);
}

// ---------------- k5: finalize BN2 affine ------------------------------------
__global__ void k_fin2(const float* __restrict__ gamma2, const float* __restrict__ beta2) {
    int f = threadIdx.x;  // 128
    float inv = 1.f / (float)N_ATOM;
    float mean = g_stats2[f] * inv;
    float var  = g_stats2[128 + f] * inv - mean * mean;
    float sc = gamma2[f] * rsqrtf(var + EPS);
    g_bn2[f] = sc;
    g_bn2[128 + f] = beta2[f] - mean * sc;
}

// ---------------- k6: out = softplus(atom + BN2(nbr_sumed)) ------------------
__global__ void k_out(const float* __restrict__ atom, float* __restrict__ out) {
    int i = blockIdx.x * blockDim.x + threadIdx.x;
    if (i < N_ATOM * 128) {
        int f = i & 127;
        float v = atom[i] + g_nbr[i] * g_bn2[f] + g_bn2[128 + f];
        out[i] = softplusf(v);
    }
}

// ---------------- launch ------------------------------------------------------
extern "C" void kernel_launch(void* const* d_in, const int* in_sizes, int n_in,
                              void* d_out, int out_size) {
    const float* atom   = (const float*)d_in[0];
    const float* nbr    = (const float*)d_in[1];
    const int*   idxraw = (const int*)d_in[2];
    const float* W      = (const float*)d_in[3];
    const float* b      = (const float*)d_in[4];
    const float* gamma1 = (const float*)d_in[5];
    const float* beta1  = (const float*)d_in[6];
    const float* gamma2 = (const float*)d_in[7];
    const float* beta2  = (const float*)d_in[8];
    float* out = (float*)d_out;

    k_detect<<<1, 256>>>(idxraw);
    k_convert<<<(NM_TOT + 255) / 256, 256>>>(idxraw);
    k_gemm_sa<<<dim3(4, (N_ATOM + 63) / 64), 256>>>(atom, W);
    k_gemm_gate<<<dim3(2, (NM_TOT + 127) / 128), 256>>>(nbr, W, b);
    k_fin1<<<1, 256>>>(gamma1, beta1);
    k_reduce<<<N_ATOM / CH, 128>>>();
    k_fin2<<<1, 128>>>(gamma2, beta2);
    k_out<<<(N_ATOM * 128 + 255) / 256, 256>>>(atom, out);
}